// round 3
// baseline (speedup 1.0000x reference)
#include <cuda_runtime.h>

// AutogradLoss: loss = (x-y)^2, d_loss = 2(x-y), sqd_loss = 2*I per sample (constant).
// Output layout: [loss (B*16) | d_loss (B*16) | sqd_loss (B*256)] floats.
// Pure HBM-write-bound: ~1.21 GB writes + 0.13 GB reads.

__global__ void loss_grad_kernel(const float4* __restrict__ x,
                                 const float4* __restrict__ y,
                                 float4* __restrict__ loss,
                                 float4* __restrict__ dloss,
                                 int n4) {
    int i = blockIdx.x * blockDim.x + threadIdx.x;
    if (i < n4) {
        float4 a = x[i];
        float4 b = y[i];
        float dx = a.x - b.x, dy = a.y - b.y, dz = a.z - b.z, dw = a.w - b.w;
        float4 l, g;
        l.x = dx * dx; l.y = dy * dy; l.z = dz * dz; l.w = dw * dw;
        g.x = 2.f * dx; g.y = 2.f * dy; g.z = 2.f * dz; g.w = 2.f * dw;
        loss[i]  = l;
        dloss[i] = g;
    }
}

// sqd_loss[b] is a 16x16 matrix = 2*I. Per sample: 256 floats = 64 float4.
// float4 index pos in [0,64): row = pos>>2, col-group = pos&3.
// The diagonal element (row,row) lives in col-group row>>2, lane row&3.
__global__ void hess_kernel(float4* __restrict__ sq, long long n4) {
    long long i = (long long)blockIdx.x * blockDim.x + threadIdx.x;
    if (i < n4) {
        int pos = (int)(i & 63);
        int row = pos >> 2;
        int grp = pos & 3;
        float4 v = make_float4(0.f, 0.f, 0.f, 0.f);
        if (grp == (row >> 2)) {
            ((float*)&v)[row & 3] = 2.0f;
        }
        sq[i] = v;
    }
}

extern "C" void kernel_launch(void* const* d_in, const int* in_sizes, int n_in,
                              void* d_out, int out_size) {
    const float* x = (const float*)d_in[0];
    const float* y = (const float*)d_in[1];
    float* out = (float*)d_out;

    long long bd = in_sizes[0];          // B*16
    long long n4_ld = bd / 4;            // float4 count for loss / d_loss
    long long n4_sq = bd * 16 / 4;       // float4 count for sqd_loss

    float* loss  = out;
    float* dloss = out + bd;
    float* sq    = out + 2 * bd;

    {
        int threads = 256;
        int blocks = (int)((n4_ld + threads - 1) / threads);
        loss_grad_kernel<<<blocks, threads>>>((const float4*)x, (const float4*)y,
                                              (float4*)loss, (float4*)dloss,
                                              (int)n4_ld);
    }
    {
        int threads = 256;
        int blocks = (int)((n4_sq + threads - 1) / threads);
        hess_kernel<<<blocks, threads>>>((float4*)sq, n4_sq);
    }
}